// round 15
// baseline (speedup 1.0000x reference)
#include <cuda_runtime.h>
#include <cuda_fp16.h>
#include <cstdint>
#include <cstddef>

#define B_   4
#define T_   448
#define TPAD 512
#define U_   448
#define SKS_ 96
#define BKS_ 32
#define H_   96
#define V_   128
#define PITCH 208          // smem row pitch (96 fp16 = 192 B + pad) -> conflict-free ldmatrix
#define LOG2E 1.4426950408889634f
#define LN2   0.6931471805599453f

// ---------------- device scratch (fp16) ----------------
__device__ __align__(16) unsigned short g_shh [B_ * TPAD * H_];  // fp16 sh
__device__ __align__(16) unsigned short g_rbhh[B_ * U_ * H_];    // fp16 relu(bh)

// ---------------- asm helpers ----------------
__device__ __forceinline__ uint32_t smem_u32(const void* p) {
    uint32_t a;
    asm("{ .reg .u64 t; cvta.to.shared.u64 t, %1; cvt.u32.u64 %0, t; }" : "=r"(a) : "l"(p));
    return a;
}
__device__ __forceinline__ float ex2f(float x) {
    float r;
    asm("ex2.approx.ftz.f32 %0, %1;" : "=f"(r) : "f"(x));
    return r;
}
#define LDSM2(r, addr) \
    asm volatile("ldmatrix.sync.aligned.m8n8.x2.shared.b16 {%0,%1}, [%2];" \
        : "=r"((r)[0]), "=r"((r)[1]) : "r"(addr))
#define LDSM4(r, addr) \
    asm volatile("ldmatrix.sync.aligned.m8n8.x4.shared.b16 {%0,%1,%2,%3}, [%4];" \
        : "=r"((r)[0]), "=r"((r)[1]), "=r"((r)[2]), "=r"((r)[3]) : "r"(addr))

#define MMA16816(c, a0, a1, a2, a3, b0, b1) \
    asm volatile("mma.sync.aligned.m16n8k16.row.col.f32.f16.f16.f32 " \
        "{%0,%1,%2,%3}, {%4,%5,%6,%7}, {%8,%9}, {%0,%1,%2,%3};" \
        : "+f"((c)[0]), "+f"((c)[1]), "+f"((c)[2]), "+f"((c)[3]) \
        : "r"(a0), "r"(a1), "r"(a2), "r"(a3), "r"(b0), "r"(b1))

__device__ __forceinline__ uint32_t hmul2u(uint32_t a, uint32_t b) {
    __half2 r = __hmul2(*reinterpret_cast<__half2*>(&a), *reinterpret_cast<__half2*>(&b));
    return *reinterpret_cast<uint32_t*>(&r);
}

// Column permutation (same as R12/R14): phys p = 8*j + 2*qe + e holds logical
// L = 16*(j>>1) + 4*qe + 2*(j&1) + e  -> lane quad = 4 consecutive logical cols.
__device__ __forceinline__ int perm_phys(int v) {
    return 16 * (v >> 4) + 8 * ((v & 3) >> 1) + 2 * ((v >> 2) & 3) + (v & 1);
}

// ============================================================================
// Input projections; outputs stored as fp16. (unchanged)
// ============================================================================
__global__ __launch_bounds__(96) void proj8(
    const float* __restrict__ s,   const float* __restrict__ bmat,
    const float* __restrict__ Wsh, const float* __restrict__ bsh,
    const float* __restrict__ Wbh, const float* __restrict__ bbh)
{
    __shared__ float sw[H_ * 97];
    __shared__ float srow[8][97];
    const int h = threadIdx.x;

    if (blockIdx.y == 0) {
        for (int i = h; i < H_ * SKS_; i += 96)
            sw[(i / SKS_) * 97 + (i % SKS_)] = Wsh[i];
        const int base = blockIdx.x * 8;
        #pragma unroll
        for (int r = 0; r < 8; r++) {
            int row = base + r, b = row >> 9, t = row & 511;
            srow[r][h] = (t < T_) ? s[((size_t)b * T_ + t) * SKS_ + h] : 0.0f;
        }
        __syncthreads();
        float acc[8];
        const float bias = bsh[h];
        #pragma unroll
        for (int r = 0; r < 8; r++) acc[r] = bias;
        #pragma unroll 4
        for (int k = 0; k < SKS_; k++) {
            float w = sw[h * 97 + k];
            #pragma unroll
            for (int r = 0; r < 8; r++) acc[r] = fmaf(srow[r][k], w, acc[r]);
        }
        #pragma unroll
        for (int r = 0; r < 8; r++) {
            __half v = __float2half_rn(acc[r]);
            g_shh[(size_t)(base + r) * H_ + h] = *reinterpret_cast<unsigned short*>(&v);
        }
    } else {
        if (blockIdx.x >= (B_ * U_) / 8) return;
        for (int i = h; i < H_ * BKS_; i += 96)
            sw[(i / BKS_) * 33 + (i % BKS_)] = Wbh[i];
        const int base = blockIdx.x * 8;
        if (h < BKS_) {
            #pragma unroll
            for (int r = 0; r < 8; r++)
                srow[r][h] = bmat[(size_t)(base + r) * BKS_ + h];
        }
        __syncthreads();
        float acc[8];
        const float bias = bbh[h];
        #pragma unroll
        for (int r = 0; r < 8; r++) acc[r] = bias;
        #pragma unroll
        for (int k = 0; k < BKS_; k++) {
            float w = sw[h * 33 + k];
            #pragma unroll
            for (int r = 0; r < 8; r++) acc[r] = fmaf(srow[r][k], w, acc[r]);
        }
        #pragma unroll
        for (int r = 0; r < 8; r++) {
            __half v = __float2half_rn(fmaxf(acc[r], 0.0f));
            g_rbhh[(size_t)(base + r) * H_ + h] = *reinterpret_cast<unsigned short*>(&v);
        }
    }
}

// ============================================================================
// Main kernel. grid (9, 28): y = (bz, 64-row t-tile) -- 448 = 7*64, so NO
// padding rows; x = u-chunk (50 u's = 25 pairs; last 48 = 24 pairs).
// ITEM PAIRING: one MMA sweep computes two u-items -- A rows 0-7 = sh⊙rbh_u0,
// rows 8-15 = sh⊙rbh_u1 (B fragments amortized over 2 items).
// Warp mg owns t-rows mg*8..+7 for BOTH items; warp-local log2-softmax;
// permuted cols -> float4 stores.
// ============================================================================
#define S_BH   0                    // [128][PITCH] fp16 W*log2e (rows permuted)
#define S_SHH  26624                // [64][PITCH] fp16 sh tile
#define S_RBH  39936                // [2][2][48] uint (half2 rbh, pair-buffered)
#define S_BIA  40704                // [128] float bias*log2e (permuted)
#define SMEM_MAIN 41216

__global__ __launch_bounds__(256, 2) void joiner_hmma(
    const float* __restrict__ Wout, const float* __restrict__ bout,
    float* __restrict__ out)
{
    extern __shared__ __align__(16) char smem[];
    const uint32_t sb = smem_u32(smem);
    const int tid = threadIdx.x;
    const int wid = tid >> 5, lid = tid & 31;
    const int mg = wid;                 // 8 warps, 8 t-rows each
    const int q  = lid >> 2, qe = lid & 3;

    const int g  = blockIdx.y;          // 0..27
    const int bz = g / 7;
    const int t0 = (g % 7) * 64;
    const int c  = blockIdx.x;          // 0..8
    const int ustart = c * 50;
    const int npairs = (c < 8) ? 25 : 24;

    // ---- one-time: stage W*log2e (rows permuted), bias*log2e, sh tile ----
    for (int idx = tid; idx < V_ * H_; idx += 256) {
        const int n = idx / H_, k = idx - n * H_;
        *(__half*)(smem + S_BH + perm_phys(n) * PITCH + k * 2) =
            __float2half_rn(Wout[idx] * LOG2E);
    }
    if (tid < V_)
        ((float*)(smem + S_BIA))[perm_phys(tid)] = bout[tid] * LOG2E;
    {
        const uint4* src = (const uint4*)(g_shh + ((size_t)(bz * TPAD) + t0) * H_);
        for (int i = tid; i < 64 * 12; i += 256) {
            const int row = i / 12, kq = i - row * 12;
            *(uint4*)(smem + S_SHH + row * PITCH + kq * 16) = src[row * 12 + kq];
        }
    }

    // ldmatrix lane addresses
    const uint32_t aoff2 = (uint32_t)((lid & 7) * PITCH + ((lid >> 3) & 1) * 16);
    const uint32_t boff  = (uint32_t)(((lid & 7) + ((lid >> 4) << 3)) * PITCH + ((lid >> 3) & 1) * 16);
    const uint32_t sAh = sb + S_SHH + (uint32_t)(mg * 8 * PITCH) + aoff2;
    const uint32_t sBh = sb + S_BH + boff;

    uint32_t* rbAll = (uint32_t*)(smem + S_RBH);     // [2][2][48]
    const float* biaL = (const float*)(smem + S_BIA) + 2 * qe;   // phys-indexed

    // prologue: rbh for first pair into buffer 0
    if (tid < 96) {
        const int which = tid / 48, idx = tid - which * 48;
        rbAll[which * 48 + idx] =
            ((const uint32_t*)(g_rbhh + ((size_t)bz * U_ + ustart + which) * H_))[idx];
    }

    int p = 0;
    for (int it = 0; it < npairs; it++, p ^= 1) {
        const int u0 = ustart + 2 * it;

        __syncthreads();   // rbh buffer p ready + tiles staged

        // prefetch next pair's rbh into a register
        uint32_t nrb = 0u;
        if (tid < 96 && it + 1 < npairs) {
            const int which = tid / 48, idx = tid - which * 48;
            nrb = ((const uint32_t*)(g_rbhh + ((size_t)bz * U_ + u0 + 2 + which) * H_))[idx];
        }

        const char* rb0B = (const char*)(rbAll + p * 96);        // item u0
        const char* rb1B = (const char*)(rbAll + p * 96 + 48);   // item u1

        float acc[16][4];
        #pragma unroll
        for (int j = 0; j < 16; j++)
            #pragma unroll
            for (int e4 = 0; e4 < 4; e4++) acc[j][e4] = 0.0f;

        // ---- 6 k-steps: A rows 0-7 = sh⊙rb_u0, rows 8-15 = sh⊙rb_u1 ----
        #pragma unroll
        for (int s = 0; s < 6; s++) {
            uint32_t r0a = *(const uint32_t*)(rb0B + s * 32 + qe * 4);        // u0, cols 2qe
            uint32_t r0b = *(const uint32_t*)(rb0B + s * 32 + 16 + qe * 4);   // u0, cols 8+2qe
            uint32_t r1a = *(const uint32_t*)(rb1B + s * 32 + qe * 4);        // u1
            uint32_t r1b = *(const uint32_t*)(rb1B + s * 32 + 16 + qe * 4);
            uint32_t am[2], ah[4];
            LDSM2(am, sAh + s * 32);          // sh row q: cols 2qe (am0), 8+2qe (am1)
            ah[0] = hmul2u(am[0], r0a);       // frag row q      (item u0)
            ah[1] = hmul2u(am[0], r1a);       // frag row q+8    (item u1)
            ah[2] = hmul2u(am[1], r0b);
            ah[3] = hmul2u(am[1], r1b);
            #pragma unroll
            for (int blk = 0; blk < 2; blk++) {
                uint32_t bq[4][4];
                #pragma unroll
                for (int jj = 0; jj < 4; jj++)
                    LDSM4(bq[jj], sBh + (blk * 4 + jj) * 16 * PITCH + s * 32);
                #pragma unroll
                for (int j8 = 0; j8 < 8; j8++)
                    MMA16816(acc[blk * 8 + j8], ah[0], ah[1], ah[2], ah[3],
                             bq[j8 >> 1][(j8 & 1) * 2], bq[j8 >> 1][(j8 & 1) * 2 + 1]);
            }
        }

        // park next pair's rbh into the other buffer
        if (tid < 96 && it + 1 < npairs) {
            const int which = tid / 48, idx = tid - which * 48;
            rbAll[(p ^ 1) * 96 + which * 48 + idx] = nrb;
        }

        // ---- bias add (phys-indexed, log2-domain; both items same bias) ----
        #pragma unroll
        for (int j = 0; j < 16; j++) {
            float2 bv = *(const float2*)(biaL + 8 * j);
            acc[j][0] += bv.x; acc[j][1] += bv.y;
            acc[j][2] += bv.x; acc[j][3] += bv.y;
        }

        // ---- warp-local log2-softmax; h=0 -> item u0, h=1 -> item u1 ----
        const int t = t0 + mg * 8 + q;
        #pragma unroll
        for (int h = 0; h < 2; h++) {
            float m = -3.4e38f;
            #pragma unroll
            for (int j = 0; j < 16; j++) {
                m = fmaxf(m, acc[j][2 * h]);
                m = fmaxf(m, acc[j][2 * h + 1]);
            }
            m = fmaxf(m, __shfl_xor_sync(0xffffffffu, m, 1));
            m = fmaxf(m, __shfl_xor_sync(0xffffffffu, m, 2));
            float ss = 0.0f;
            #pragma unroll
            for (int j = 0; j < 16; j++)
                ss += ex2f(acc[j][2 * h] - m) + ex2f(acc[j][2 * h + 1] - m);
            ss += __shfl_xor_sync(0xffffffffu, ss, 1);
            ss += __shfl_xor_sync(0xffffffffu, ss, 2);
            const float lsel = (m + __log2f(ss)) * LN2;

            float* orow = out + (((size_t)bz * T_ + t) * U_ + (u0 + h)) * V_ + 4 * qe;
            #pragma unroll
            for (int m2 = 0; m2 < 8; m2++) {
                float4 v;
                v.x = fmaf(acc[2 * m2][2 * h],     LN2, -lsel);
                v.y = fmaf(acc[2 * m2][2 * h + 1], LN2, -lsel);
                v.z = fmaf(acc[2 * m2 + 1][2 * h],     LN2, -lsel);
                v.w = fmaf(acc[2 * m2 + 1][2 * h + 1], LN2, -lsel);
                *(float4*)(orow + 16 * m2) = v;
            }
        }
    }
}

extern "C" void kernel_launch(void* const* d_in, const int* in_sizes, int n_in,
                              void* d_out, int out_size)
{
    (void)in_sizes; (void)n_in; (void)out_size;
    const float* s    = (const float*)d_in[0];
    const float* bmat = (const float*)d_in[1];
    const float* Wsh  = (const float*)d_in[2];
    const float* bsh  = (const float*)d_in[3];
    const float* Wbh  = (const float*)d_in[4];
    const float* bbh  = (const float*)d_in[5];
    const float* Wout = (const float*)d_in[6];
    const float* bout = (const float*)d_in[7];
    float* out = (float*)d_out;

    cudaFuncSetAttribute(joiner_hmma,
                         cudaFuncAttributeMaxDynamicSharedMemorySize, SMEM_MAIN);

    proj8<<<dim3((B_ * TPAD) / 8, 2), 96>>>(s, bmat, Wsh, bsh, Wbh, bbh);
    joiner_hmma<<<dim3(9, 28), 256, SMEM_MAIN>>>(Wout, bout, out);
}

// round 17
// speedup vs baseline: 1.0745x; 1.0745x over previous
#include <cuda_runtime.h>
#include <cuda_fp16.h>
#include <cstdint>
#include <cstddef>

#define B_   4
#define T_   448
#define TPAD 512
#define U_   448
#define SKS_ 96
#define BKS_ 32
#define H_   96
#define V_   128
#define PITCH 208          // smem row pitch (96 fp16 = 192 B + pad) -> conflict-free ldmatrix
#define LOG2E 1.4426950408889634f
#define LN2   0.6931471805599453f

#define NGROUPS   (B_ * 7)          // 28 (bz, 64-row t-tile) groups, no padding
#define PAIRS_PG  (U_ / 2)          // 224 u-pairs per group
#define NPAIRS    (NGROUPS * PAIRS_PG)   // 6272
#define GRID_MAIN 296               // 2 CTAs/SM exactly, one wave

// ---------------- device scratch (fp16) ----------------
__device__ __align__(16) unsigned short g_shh [B_ * TPAD * H_];  // fp16 sh
__device__ __align__(16) unsigned short g_rbhh[B_ * U_ * H_];    // fp16 relu(bh)

// ---------------- asm helpers ----------------
__device__ __forceinline__ uint32_t smem_u32(const void* p) {
    uint32_t a;
    asm("{ .reg .u64 t; cvta.to.shared.u64 t, %1; cvt.u32.u64 %0, t; }" : "=r"(a) : "l"(p));
    return a;
}
__device__ __forceinline__ float ex2f(float x) {
    float r;
    asm("ex2.approx.ftz.f32 %0, %1;" : "=f"(r) : "f"(x));
    return r;
}
#define LDSM2(r, addr) \
    asm volatile("ldmatrix.sync.aligned.m8n8.x2.shared.b16 {%0,%1}, [%2];" \
        : "=r"((r)[0]), "=r"((r)[1]) : "r"(addr))
#define LDSM4(r, addr) \
    asm volatile("ldmatrix.sync.aligned.m8n8.x4.shared.b16 {%0,%1,%2,%3}, [%4];" \
        : "=r"((r)[0]), "=r"((r)[1]), "=r"((r)[2]), "=r"((r)[3]) : "r"(addr))

#define MMA16816(c, a0, a1, a2, a3, b0, b1) \
    asm volatile("mma.sync.aligned.m16n8k16.row.col.f32.f16.f16.f32 " \
        "{%0,%1,%2,%3}, {%4,%5,%6,%7}, {%8,%9}, {%0,%1,%2,%3};" \
        : "+f"((c)[0]), "+f"((c)[1]), "+f"((c)[2]), "+f"((c)[3]) \
        : "r"(a0), "r"(a1), "r"(a2), "r"(a3), "r"(b0), "r"(b1))

__device__ __forceinline__ uint32_t hmul2u(uint32_t a, uint32_t b) {
    __half2 r = __hmul2(*reinterpret_cast<__half2*>(&a), *reinterpret_cast<__half2*>(&b));
    return *reinterpret_cast<uint32_t*>(&r);
}

// Column permutation: phys p = 8*j + 2*qe + e holds logical
// L = 16*(j>>1) + 4*qe + 2*(j&1) + e  -> lane quad = 4 consecutive logical cols.
__device__ __forceinline__ int perm_phys(int v) {
    return 16 * (v >> 4) + 8 * ((v & 3) >> 1) + 2 * ((v >> 2) & 3) + (v & 1);
}

// ============================================================================
// Input projections; outputs stored as fp16. (unchanged)
// ============================================================================
__global__ __launch_bounds__(96) void proj8(
    const float* __restrict__ s,   const float* __restrict__ bmat,
    const float* __restrict__ Wsh, const float* __restrict__ bsh,
    const float* __restrict__ Wbh, const float* __restrict__ bbh)
{
    __shared__ float sw[H_ * 97];
    __shared__ float srow[8][97];
    const int h = threadIdx.x;

    if (blockIdx.y == 0) {
        for (int i = h; i < H_ * SKS_; i += 96)
            sw[(i / SKS_) * 97 + (i % SKS_)] = Wsh[i];
        const int base = blockIdx.x * 8;
        #pragma unroll
        for (int r = 0; r < 8; r++) {
            int row = base + r, b = row >> 9, t = row & 511;
            srow[r][h] = (t < T_) ? s[((size_t)b * T_ + t) * SKS_ + h] : 0.0f;
        }
        __syncthreads();
        float acc[8];
        const float bias = bsh[h];
        #pragma unroll
        for (int r = 0; r < 8; r++) acc[r] = bias;
        #pragma unroll 4
        for (int k = 0; k < SKS_; k++) {
            float w = sw[h * 97 + k];
            #pragma unroll
            for (int r = 0; r < 8; r++) acc[r] = fmaf(srow[r][k], w, acc[r]);
        }
        #pragma unroll
        for (int r = 0; r < 8; r++) {
            __half v = __float2half_rn(acc[r]);
            g_shh[(size_t)(base + r) * H_ + h] = *reinterpret_cast<unsigned short*>(&v);
        }
    } else {
        if (blockIdx.x >= (B_ * U_) / 8) return;
        for (int i = h; i < H_ * BKS_; i += 96)
            sw[(i / BKS_) * 33 + (i % BKS_)] = Wbh[i];
        const int base = blockIdx.x * 8;
        if (h < BKS_) {
            #pragma unroll
            for (int r = 0; r < 8; r++)
                srow[r][h] = bmat[(size_t)(base + r) * BKS_ + h];
        }
        __syncthreads();
        float acc[8];
        const float bias = bbh[h];
        #pragma unroll
        for (int r = 0; r < 8; r++) acc[r] = bias;
        #pragma unroll
        for (int k = 0; k < BKS_; k++) {
            float w = sw[h * 33 + k];
            #pragma unroll
            for (int r = 0; r < 8; r++) acc[r] = fmaf(srow[r][k], w, acc[r]);
        }
        #pragma unroll
        for (int r = 0; r < 8; r++) {
            __half v = __float2half_rn(fmaxf(acc[r], 0.0f));
            g_rbhh[(size_t)(base + r) * H_ + h] = *reinterpret_cast<unsigned short*>(&v);
        }
    }
}

// ============================================================================
// Main kernel. Flat grid of 296 CTAs (2/SM, one wave); each CTA processes a
// contiguous chunk of the global pair list (21-22 pairs, perfectly balanced).
// A chunk crosses at most one (bz,t0) group boundary -> sh tile re-staged at
// most once per CTA. Pair body identical to R15 (item-paired MMA, warp-local
// log2-softmax, permuted float4 stores).
// ============================================================================
#define S_BH   0                    // [128][PITCH] fp16 W*log2e (rows permuted)
#define S_SHH  26624                // [64][PITCH] fp16 sh tile (current group)
#define S_RBH  39936                // [2][2][48] uint (half2 rbh, pair-buffered)
#define S_BIA  40704                // [128] float bias*log2e (permuted)
#define SMEM_MAIN 41216

__global__ __launch_bounds__(256, 2) void joiner_hmma(
    const float* __restrict__ Wout, const float* __restrict__ bout,
    float* __restrict__ out)
{
    extern __shared__ __align__(16) char smem[];
    const uint32_t sb = smem_u32(smem);
    const int tid = threadIdx.x;
    const int wid = tid >> 5, lid = tid & 31;
    const int mg = wid;                 // 8 warps, 8 t-rows each
    const int q  = lid >> 2, qe = lid & 3;

    // balanced contiguous chunk of pairs
    const int cta = blockIdx.x;
    const int pbeg = (int)(((long long)cta * NPAIRS) / GRID_MAIN);
    const int pend = (int)(((long long)(cta + 1) * NPAIRS) / GRID_MAIN);

    // ---- one-time: stage W*log2e (rows permuted) + bias*log2e ----
    for (int idx = tid; idx < V_ * H_; idx += 256) {
        const int n = idx / H_, k = idx - n * H_;
        *(__half*)(smem + S_BH + perm_phys(n) * PITCH + k * 2) =
            __float2half_rn(Wout[idx] * LOG2E);
    }
    if (tid < V_)
        ((float*)(smem + S_BIA))[perm_phys(tid)] = bout[tid] * LOG2E;

    // ldmatrix lane addresses
    const uint32_t aoff2 = (uint32_t)((lid & 7) * PITCH + ((lid >> 3) & 1) * 16);
    const uint32_t boff  = (uint32_t)(((lid & 7) + ((lid >> 4) << 3)) * PITCH + ((lid >> 3) & 1) * 16);
    const uint32_t sAh = sb + S_SHH + (uint32_t)(mg * 8 * PITCH) + aoff2;
    const uint32_t sBh = sb + S_BH + boff;

    uint32_t* rbAll = (uint32_t*)(smem + S_RBH);     // [2][2][48]
    const float* biaL = (const float*)(smem + S_BIA) + 2 * qe;

    // prologue: rbh for first pair into buffer 0
    {
        const int gg = pbeg / PAIRS_PG, k0 = pbeg - gg * PAIRS_PG;
        const int bz0 = gg / 7;
        if (tid < 96) {
            const int which = tid / 48, idx = tid - which * 48;
            rbAll[which * 48 + idx] =
                ((const uint32_t*)(g_rbhh + ((size_t)bz0 * U_ + 2 * k0 + which) * H_))[idx];
        }
    }

    int curgroup = -1;
    int p = 0;
    for (int pid = pbeg; pid < pend; pid++, p ^= 1) {
        const int gg = pid / PAIRS_PG;
        const int k  = pid - gg * PAIRS_PG;
        const int bz = gg / 7;
        const int t0 = (gg - bz * 7) * 64;
        const int u0 = 2 * k;

        __syncthreads();   // rbh buffer p published; prev item's smem reads done

        if (gg != curgroup) {
            // (re)stage sh tile for this group — happens at most twice per CTA
            const uint4* src = (const uint4*)(g_shh + ((size_t)(bz * TPAD) + t0) * H_);
            for (int i = tid; i < 64 * 12; i += 256) {
                const int row = i / 12, kq = i - row * 12;
                *(uint4*)(smem + S_SHH + row * PITCH + kq * 16) = src[row * 12 + kq];
            }
            curgroup = gg;
            __syncthreads();
        }

        // prefetch next pair's rbh into a register
        uint32_t nrb = 0u;
        if (tid < 96 && pid + 1 < pend) {
            const int ng = (pid + 1) / PAIRS_PG;
            const int nk = (pid + 1) - ng * PAIRS_PG;
            const int nbz = ng / 7;
            const int which = tid / 48, idx = tid - which * 48;
            nrb = ((const uint32_t*)(g_rbhh + ((size_t)nbz * U_ + 2 * nk + which) * H_))[idx];
        }

        const char* rb0B = (const char*)(rbAll + p * 96);        // item u0
        const char* rb1B = (const char*)(rbAll + p * 96 + 48);   // item u1

        float acc[16][4];
        #pragma unroll
        for (int j = 0; j < 16; j++)
            #pragma unroll
            for (int e4 = 0; e4 < 4; e4++) acc[j][e4] = 0.0f;

        // ---- 6 k-steps: A rows 0-7 = sh⊙rb_u0, rows 8-15 = sh⊙rb_u1 ----
        #pragma unroll
        for (int s = 0; s < 6; s++) {
            uint32_t r0a = *(const uint32_t*)(rb0B + s * 32 + qe * 4);
            uint32_t r0b = *(const uint32_t*)(rb0B + s * 32 + 16 + qe * 4);
            uint32_t r1a = *(const uint32_t*)(rb1B + s * 32 + qe * 4);
            uint32_t r1b = *(const uint32_t*)(rb1B + s * 32 + 16 + qe * 4);
            uint32_t am[2], ah[4];
            LDSM2(am, sAh + s * 32);
            ah[0] = hmul2u(am[0], r0a);       // frag row q      (item u0)
            ah[1] = hmul2u(am[0], r1a);       // frag row q+8    (item u1)
            ah[2] = hmul2u(am[1], r0b);
            ah[3] = hmul2u(am[1], r1b);
            #pragma unroll
            for (int blk = 0; blk < 2; blk++) {
                uint32_t bq[4][4];
                #pragma unroll
                for (int jj = 0; jj < 4; jj++)
                    LDSM4(bq[jj], sBh + (blk * 4 + jj) * 16 * PITCH + s * 32);
                #pragma unroll
                for (int j8 = 0; j8 < 8; j8++)
                    MMA16816(acc[blk * 8 + j8], ah[0], ah[1], ah[2], ah[3],
                             bq[j8 >> 1][(j8 & 1) * 2], bq[j8 >> 1][(j8 & 1) * 2 + 1]);
            }
        }

        // park next pair's rbh into the other buffer
        if (tid < 96 && pid + 1 < pend) {
            const int which = tid / 48, idx = tid - which * 48;
            rbAll[(p ^ 1) * 96 + which * 48 + idx] = nrb;
        }

        // ---- bias add (phys-indexed, log2-domain) ----
        #pragma unroll
        for (int j = 0; j < 16; j++) {
            float2 bv = *(const float2*)(biaL + 8 * j);
            acc[j][0] += bv.x; acc[j][1] += bv.y;
            acc[j][2] += bv.x; acc[j][3] += bv.y;
        }

        // ---- warp-local log2-softmax; h=0 -> item u0, h=1 -> item u1 ----
        const int t = t0 + mg * 8 + q;
        #pragma unroll
        for (int h = 0; h < 2; h++) {
            float m = -3.4e38f;
            #pragma unroll
            for (int j = 0; j < 16; j++) {
                m = fmaxf(m, acc[j][2 * h]);
                m = fmaxf(m, acc[j][2 * h + 1]);
            }
            m = fmaxf(m, __shfl_xor_sync(0xffffffffu, m, 1));
            m = fmaxf(m, __shfl_xor_sync(0xffffffffu, m, 2));
            float ss = 0.0f;
            #pragma unroll
            for (int j = 0; j < 16; j++)
                ss += ex2f(acc[j][2 * h] - m) + ex2f(acc[j][2 * h + 1] - m);
            ss += __shfl_xor_sync(0xffffffffu, ss, 1);
            ss += __shfl_xor_sync(0xffffffffu, ss, 2);
            const float lsel = (m + __log2f(ss)) * LN2;

            float* orow = out + (((size_t)bz * T_ + t) * U_ + (u0 + h)) * V_ + 4 * qe;
            #pragma unroll
            for (int m2 = 0; m2 < 8; m2++) {
                float4 v;
                v.x = fmaf(acc[2 * m2][2 * h],     LN2, -lsel);
                v.y = fmaf(acc[2 * m2][2 * h + 1], LN2, -lsel);
                v.z = fmaf(acc[2 * m2 + 1][2 * h],     LN2, -lsel);
                v.w = fmaf(acc[2 * m2 + 1][2 * h + 1], LN2, -lsel);
                *(float4*)(orow + 16 * m2) = v;
            }
        }
    }
}

extern "C" void kernel_launch(void* const* d_in, const int* in_sizes, int n_in,
                              void* d_out, int out_size)
{
    (void)in_sizes; (void)n_in; (void)out_size;
    const float* s    = (const float*)d_in[0];
    const float* bmat = (const float*)d_in[1];
    const float* Wsh  = (const float*)d_in[2];
    const float* bsh  = (const float*)d_in[3];
    const float* Wbh  = (const float*)d_in[4];
    const float* bbh  = (const float*)d_in[5];
    const float* Wout = (const float*)d_in[6];
    const float* bout = (const float*)d_in[7];
    float* out = (float*)d_out;

    cudaFuncSetAttribute(joiner_hmma,
                         cudaFuncAttributeMaxDynamicSharedMemorySize, SMEM_MAIN);

    proj8<<<dim3((B_ * TPAD) / 8, 2), 96>>>(s, bmat, Wsh, bsh, Wbh, bbh);
    joiner_hmma<<<GRID_MAIN, 256, SMEM_MAIN>>>(Wout, bout, out);
}